// round 1
// baseline (speedup 1.0000x reference)
#include <cuda_runtime.h>
#include <math.h>

// Problem constants (fixed shapes per reference)
#define B_DIM 16
#define K_DIM 64
#define H_DIM 96
#define W_DIM 96
#define HW    (H_DIM * W_DIM)            // 9216
#define MAPS  (B_DIM * K_DIM)            // 1024
#define DK_ELEMS ((size_t)MAPS * HW)     // 9,437,184 per stack
#define KP_ELEMS ((size_t)B_DIM * 3 * K_DIM * 2)  // 6144 per stack
#define Z_ELEMS  ((size_t)B_DIM * K_DIM)          // 1024 per stack

// One block per (stack, b, k) heatmap: 256 threads, 9 float4 iterations each.
// Fuses sigmoid (elementwise output) with zeta/kx/ky reductions, then thread 0
// does the soft-argmax decode: round, gather (recompute sigmoid of one input
// element with precise expf), trunc(kp +/- kp*d), and writes keypoints + zeta.
__global__ __launch_bounds__(256, 4)
void dcm2kp_kernel(const float* __restrict__ Rk,
                   const float* __restrict__ tfRk,
                   float* __restrict__ out)
{
    const int bid = blockIdx.x;          // [0, 2048)
    const int s   = bid >> 10;           // stack: 0 = Rk, 1 = tf_Rk
    const int bk  = bid & 1023;          // map index within stack

    const float* __restrict__ in = (s ? tfRk : Rk) + (size_t)bk * HW;
    float* __restrict__ dkout = out + (size_t)s * DK_ELEMS + (size_t)bk * HW;

    const int t = threadIdx.x;

    float zs = 0.0f, kxs = 0.0f, kys = 0.0f;

    const float4* __restrict__ in4 = reinterpret_cast<const float4*>(in);
    float4* __restrict__ out4 = reinterpret_cast<float4*>(dkout);

    #pragma unroll
    for (int it = 0; it < 9; ++it) {
        const int j = t + it * 256;      // float4 index, [0, 2304)
        const int e = j << 2;            // element index, [0, 9216)
        float4 v = in4[j];

        // fast sigmoid (MUFU EX2 + RCP); rel err ~5e-7, fine for 1e-3 tol
        float d0 = 1.0f / (1.0f + __expf(-v.x));
        float d1 = 1.0f / (1.0f + __expf(-v.y));
        float d2 = 1.0f / (1.0f + __expf(-v.z));
        float d3 = 1.0f / (1.0f + __expf(-v.w));

        out4[j] = make_float4(d0, d1, d2, d3);

        // 4 consecutive elements share the row (96 % 4 == 0, e % 4 == 0)
        const int h  = e / 96;
        const int w0 = e - h * 96;

        const float s4 = (d0 + d1) + (d2 + d3);
        zs  += s4;
        kxs += (float)w0 * s4 + (d1 + 2.0f * d2 + 3.0f * d3);
        kys += (float)h * s4;
    }

    // warp reduce (f32)
    #pragma unroll
    for (int o = 16; o > 0; o >>= 1) {
        zs  += __shfl_down_sync(0xffffffffu, zs,  o);
        kxs += __shfl_down_sync(0xffffffffu, kxs, o);
        kys += __shfl_down_sync(0xffffffffu, kys, o);
    }

    __shared__ double sz[8], sx[8], sy[8];
    const int wid = t >> 5, lid = t & 31;
    if (lid == 0) { sz[wid] = (double)zs; sx[wid] = (double)kxs; sy[wid] = (double)kys; }
    __syncthreads();

    if (t == 0) {
        double z = 0.0, x = 0.0, y = 0.0;
        #pragma unroll
        for (int i = 0; i < 8; ++i) { z += sz[i]; x += sx[i]; y += sy[i]; }

        // jnp.round == round-half-to-even == rintf (default rounding mode)
        const float xr = rintf((float)(x / z));
        const float yr = rintf((float)(y / z));

        int wi = (int)xr; wi = wi < 0 ? 0 : (wi > 95 ? 95 : wi);
        int hi = (int)yr; hi = hi < 0 ? 0 : (hi > 95 ? 95 : hi);

        // gathered d: precise sigmoid (trunc boundaries are sensitive)
        const float d = 1.0f / (1.0f + expf(-in[hi * 96 + wi]));

        const int b = bk >> 6;   // bk / 64
        const int k = bk & 63;   // bk % 64

        float* __restrict__ kpbase = out + 2 * DK_ELEMS + (size_t)s * KP_ELEMS
                                   + (size_t)b * (3 * K_DIM * 2);
        float* __restrict__ zbase  = out + 2 * DK_ELEMS + 2 * KP_ELEMS
                                   + (size_t)s * Z_ELEMS;

        // kp
        kpbase[k * 2 + 0] = xr;
        kpbase[k * 2 + 1] = yr;
        // kp1 = trunc(kp + kp*d)
        kpbase[(K_DIM + k) * 2 + 0] = truncf(xr + xr * d);
        kpbase[(K_DIM + k) * 2 + 1] = truncf(yr + yr * d);
        // kp2 = trunc(kp - kp*d)
        kpbase[(2 * K_DIM + k) * 2 + 0] = truncf(xr - xr * d);
        kpbase[(2 * K_DIM + k) * 2 + 1] = truncf(yr - yr * d);

        zbase[b * K_DIM + k] = (float)z;
    }
}

extern "C" void kernel_launch(void* const* d_in, const int* in_sizes, int n_in,
                              void* d_out, int out_size)
{
    (void)in_sizes; (void)n_in; (void)out_size;
    const float* Rk   = (const float*)d_in[0];
    const float* tfRk = (const float*)d_in[1];
    float* out = (float*)d_out;

    dcm2kp_kernel<<<2 * MAPS, 256>>>(Rk, tfRk, out);
}

// round 3
// speedup vs baseline: 1.1963x; 1.1963x over previous
#include <cuda_runtime.h>
#include <math.h>

// Problem constants (fixed shapes per reference)
#define B_DIM 16
#define K_DIM 64
#define H_DIM 96
#define W_DIM 96
#define HW    (H_DIM * W_DIM)            // 9216
#define MAPS  (B_DIM * K_DIM)            // 1024
#define DK_ELEMS ((size_t)MAPS * HW)     // 9,437,184 per stack
#define KP_ELEMS ((size_t)B_DIM * 3 * K_DIM * 2)  // 6144 per stack
#define Z_ELEMS  ((size_t)B_DIM * K_DIM)          // 1024 per stack

// One block per (stack, b, k) heatmap: 256 threads x 9 float4 each.
// Phase structure maximizes memory-level parallelism:
//   P1: all 9 LDG.128 issued back-to-back (MLP=9/thread)
//   P2: 36 sigmoids + reduction accumulate (compute, no memory)
//   P3: all 9 STG.128 issued back-to-back
//   P4: block reduce + thread-0 soft-argmax decode tail
__global__ __launch_bounds__(256)
void dcm2kp_kernel(const float* __restrict__ Rk,
                   const float* __restrict__ tfRk,
                   float* __restrict__ out)
{
    const int bid = blockIdx.x;          // [0, 2048)
    const int s   = bid >> 10;           // stack: 0 = Rk, 1 = tf_Rk
    const int bk  = bid & 1023;          // map index within stack

    const float* __restrict__ in = (s ? tfRk : Rk) + (size_t)bk * HW;
    float* __restrict__ dkout = out + (size_t)s * DK_ELEMS + (size_t)bk * HW;

    const int t = threadIdx.x;

    const float4* __restrict__ in4 = reinterpret_cast<const float4*>(in);
    float4* __restrict__ out4 = reinterpret_cast<float4*>(dkout);

    // ---- Phase 1: batch ALL loads up front (MLP = 9 per thread) ----
    float4 v[9];
    #pragma unroll
    for (int it = 0; it < 9; ++it) {
        v[it] = __ldcs(&in4[t + it * 256]);   // streaming: no reuse
    }

    // ---- Phase 2: sigmoid + accumulate (pure compute) ----
    float4 d[9];
    float zs = 0.0f, kxs = 0.0f, kys = 0.0f;

    #pragma unroll
    for (int it = 0; it < 9; ++it) {
        const int e = (t + it * 256) << 2;   // element index, [0, 9216)

        // fast sigmoid (MUFU EX2 + RCP); rel err ~5e-7, fine for 1e-3 tol
        const float d0 = 1.0f / (1.0f + __expf(-v[it].x));
        const float d1 = 1.0f / (1.0f + __expf(-v[it].y));
        const float d2 = 1.0f / (1.0f + __expf(-v[it].z));
        const float d3 = 1.0f / (1.0f + __expf(-v[it].w));
        d[it] = make_float4(d0, d1, d2, d3);

        // 4 consecutive elements share the row (96 % 4 == 0, e % 4 == 0)
        const int h  = e / 96;
        const int w0 = e - h * 96;

        const float s4 = (d0 + d1) + (d2 + d3);
        zs  += s4;
        kxs += (float)w0 * s4 + (d1 + 2.0f * d2 + 3.0f * d3);
        kys += (float)h * s4;
    }

    // ---- Phase 3: batch all stores (streaming) ----
    #pragma unroll
    for (int it = 0; it < 9; ++it) {
        __stcs(&out4[t + it * 256], d[it]);
    }

    // ---- Phase 4: block reduction ----
    #pragma unroll
    for (int o = 16; o > 0; o >>= 1) {
        zs  += __shfl_down_sync(0xffffffffu, zs,  o);
        kxs += __shfl_down_sync(0xffffffffu, kxs, o);
        kys += __shfl_down_sync(0xffffffffu, kys, o);
    }

    __shared__ double sz[8], sx[8], sy[8];
    const int wid = t >> 5, lid = t & 31;
    if (lid == 0) { sz[wid] = (double)zs; sx[wid] = (double)kxs; sy[wid] = (double)kys; }
    __syncthreads();

    // ---- Phase 5: decode tail (thread 0) ----
    if (t == 0) {
        double z = 0.0, x = 0.0, y = 0.0;
        #pragma unroll
        for (int i = 0; i < 8; ++i) { z += sz[i]; x += sx[i]; y += sy[i]; }

        // jnp.round == round-half-to-even == rintf (default rounding mode)
        const float xr = rintf((float)(x / z));
        const float yr = rintf((float)(y / z));

        int wi = (int)xr; wi = wi < 0 ? 0 : (wi > 95 ? 95 : wi);
        int hi = (int)yr; hi = hi < 0 ? 0 : (hi > 95 ? 95 : hi);

        // gathered d: precise sigmoid (trunc boundaries are sensitive)
        const float dg = 1.0f / (1.0f + expf(-in[hi * 96 + wi]));

        const int b = bk >> 6;   // bk / 64
        const int k = bk & 63;   // bk % 64

        float* __restrict__ kpbase = out + 2 * DK_ELEMS + (size_t)s * KP_ELEMS
                                   + (size_t)b * (3 * K_DIM * 2);
        float* __restrict__ zbase  = out + 2 * DK_ELEMS + 2 * KP_ELEMS
                                   + (size_t)s * Z_ELEMS;

        // kp
        kpbase[k * 2 + 0] = xr;
        kpbase[k * 2 + 1] = yr;
        // kp1 = trunc(kp + kp*d)
        kpbase[(K_DIM + k) * 2 + 0] = truncf(xr + xr * dg);
        kpbase[(K_DIM + k) * 2 + 1] = truncf(yr + yr * dg);
        // kp2 = trunc(kp - kp*d)
        kpbase[(2 * K_DIM + k) * 2 + 0] = truncf(xr - xr * dg);
        kpbase[(2 * K_DIM + k) * 2 + 1] = truncf(yr - yr * dg);

        zbase[b * K_DIM + k] = (float)z;
    }
}

extern "C" void kernel_launch(void* const* d_in, const int* in_sizes, int n_in,
                              void* d_out, int out_size)
{
    (void)in_sizes; (void)n_in; (void)out_size;
    const float* Rk   = (const float*)d_in[0];
    const float* tfRk = (const float*)d_in[1];
    float* out = (float*)d_out;

    dcm2kp_kernel<<<2 * MAPS, 256>>>(Rk, tfRk, out);
}

// round 4
// speedup vs baseline: 1.2455x; 1.0411x over previous
#include <cuda_runtime.h>
#include <math.h>

// Problem constants (fixed shapes per reference)
#define B_DIM 16
#define K_DIM 64
#define H_DIM 96
#define W_DIM 96
#define HW    (H_DIM * W_DIM)            // 9216
#define MAPS  (B_DIM * K_DIM)            // 1024
#define DK_ELEMS ((size_t)MAPS * HW)     // 9,437,184 per stack
#define KP_ELEMS ((size_t)B_DIM * 3 * K_DIM * 2)  // 6144 per stack
#define Z_ELEMS  ((size_t)B_DIM * K_DIM)          // 1024 per stack

// One block per (stack, b, k) heatmap: 256 threads x 9 float4 each.
//   P1: all 9 LDG.128 issued back-to-back (MLP=9/thread), evict-first (__ldcs)
//   P2: per-iteration sigmoid -> STORE IMMEDIATELY (default policy: the 75.5MB
//       output stream fits L2 and stays resident across graph replays) ->
//       accumulate. Immediate store keeps d* temporaries dead after each
//       iteration => ~48 regs => 5 blocks/SM instead of 4.
//   P3: block reduce + thread-0 soft-argmax decode tail
__global__ __launch_bounds__(256)
void dcm2kp_kernel(const float* __restrict__ Rk,
                   const float* __restrict__ tfRk,
                   float* __restrict__ out)
{
    const int bid = blockIdx.x;          // [0, 2048)
    const int s   = bid >> 10;           // stack: 0 = Rk, 1 = tf_Rk
    const int bk  = bid & 1023;          // map index within stack

    const float* __restrict__ in = (s ? tfRk : Rk) + (size_t)bk * HW;
    float* __restrict__ dkout = out + (size_t)s * DK_ELEMS + (size_t)bk * HW;

    const int t = threadIdx.x;

    const float4* __restrict__ in4 = reinterpret_cast<const float4*>(in);
    float4* __restrict__ out4 = reinterpret_cast<float4*>(dkout);

    // ---- Phase 1: batch ALL loads up front (MLP = 9 per thread) ----
    float4 v[9];
    #pragma unroll
    for (int it = 0; it < 9; ++it) {
        v[it] = __ldcs(&in4[t + it * 256]);   // streaming read: no reuse
    }

    // ---- Phase 2: sigmoid -> immediate store -> accumulate ----
    float zs = 0.0f, kxs = 0.0f, kys = 0.0f;

    #pragma unroll
    for (int it = 0; it < 9; ++it) {
        const int j = t + it * 256;          // float4 index, [0, 2304)
        const int e = j << 2;                // element index, [0, 9216)

        // fast sigmoid (MUFU EX2 + RCP); rel err ~5e-7, fine for 1e-3 tol
        const float d0 = 1.0f / (1.0f + __expf(-v[it].x));
        const float d1 = 1.0f / (1.0f + __expf(-v[it].y));
        const float d2 = 1.0f / (1.0f + __expf(-v[it].z));
        const float d3 = 1.0f / (1.0f + __expf(-v[it].w));

        out4[j] = make_float4(d0, d1, d2, d3);   // default policy: L2-resident

        // 4 consecutive elements share the row (96 % 4 == 0, e % 4 == 0)
        const int h  = e / 96;
        const int w0 = e - h * 96;

        const float s4 = (d0 + d1) + (d2 + d3);
        zs  += s4;
        kxs += (float)w0 * s4 + (d1 + 2.0f * d2 + 3.0f * d3);
        kys += (float)h * s4;
    }

    // ---- Phase 3: block reduction ----
    #pragma unroll
    for (int o = 16; o > 0; o >>= 1) {
        zs  += __shfl_down_sync(0xffffffffu, zs,  o);
        kxs += __shfl_down_sync(0xffffffffu, kxs, o);
        kys += __shfl_down_sync(0xffffffffu, kys, o);
    }

    __shared__ double sz[8], sx[8], sy[8];
    const int wid = t >> 5, lid = t & 31;
    if (lid == 0) { sz[wid] = (double)zs; sx[wid] = (double)kxs; sy[wid] = (double)kys; }
    __syncthreads();

    // ---- Phase 4: decode tail (thread 0) ----
    if (t == 0) {
        double z = 0.0, x = 0.0, y = 0.0;
        #pragma unroll
        for (int i = 0; i < 8; ++i) { z += sz[i]; x += sx[i]; y += sy[i]; }

        // jnp.round == round-half-to-even == rintf (default rounding mode)
        const float xr = rintf((float)(x / z));
        const float yr = rintf((float)(y / z));

        int wi = (int)xr; wi = wi < 0 ? 0 : (wi > 95 ? 95 : wi);
        int hi = (int)yr; hi = hi < 0 ? 0 : (hi > 95 ? 95 : hi);

        // gathered d: precise sigmoid (trunc boundaries are sensitive)
        const float dg = 1.0f / (1.0f + expf(-in[hi * 96 + wi]));

        const int b = bk >> 6;   // bk / 64
        const int k = bk & 63;   // bk % 64

        float* __restrict__ kpbase = out + 2 * DK_ELEMS + (size_t)s * KP_ELEMS
                                   + (size_t)b * (3 * K_DIM * 2);
        float* __restrict__ zbase  = out + 2 * DK_ELEMS + 2 * KP_ELEMS
                                   + (size_t)s * Z_ELEMS;

        // kp
        kpbase[k * 2 + 0] = xr;
        kpbase[k * 2 + 1] = yr;
        // kp1 = trunc(kp + kp*d)
        kpbase[(K_DIM + k) * 2 + 0] = truncf(xr + xr * dg);
        kpbase[(K_DIM + k) * 2 + 1] = truncf(yr + yr * dg);
        // kp2 = trunc(kp - kp*d)
        kpbase[(2 * K_DIM + k) * 2 + 0] = truncf(xr - xr * dg);
        kpbase[(2 * K_DIM + k) * 2 + 1] = truncf(yr - yr * dg);

        zbase[b * K_DIM + k] = (float)z;
    }
}

extern "C" void kernel_launch(void* const* d_in, const int* in_sizes, int n_in,
                              void* d_out, int out_size)
{
    (void)in_sizes; (void)n_in; (void)out_size;
    const float* Rk   = (const float*)d_in[0];
    const float* tfRk = (const float*)d_in[1];
    float* out = (float*)d_out;

    dcm2kp_kernel<<<2 * MAPS, 256>>>(Rk, tfRk, out);
}

// round 5
// speedup vs baseline: 1.3361x; 1.0727x over previous
#include <cuda_runtime.h>
#include <math.h>

// Problem constants (fixed shapes per reference)
#define B_DIM 16
#define K_DIM 64
#define H_DIM 96
#define W_DIM 96
#define HW    (H_DIM * W_DIM)            // 9216
#define MAPS  (B_DIM * K_DIM)            // 1024
#define DK_ELEMS ((size_t)MAPS * HW)     // 9,437,184 per stack
#define KP_ELEMS ((size_t)B_DIM * 3 * K_DIM * 2)  // 6144 per stack
#define Z_ELEMS  ((size_t)B_DIM * K_DIM)          // 1024 per stack

#define NTHREADS 384                     // 12 warps; 2304 float4 = 384 * 6
#define NIT      6

// One block per (stack, b, k) heatmap: 384 threads x 6 float4 each.
// Rebalanced from 256x9: more warps (48/SM at 4 blocks) with moderate MLP=6
// beats few warps with MLP=9 for latency hiding. __launch_bounds__(384,4)
// caps regs at 42 to guarantee 4 blocks/SM (75% theoretical occupancy).
__global__ __launch_bounds__(NTHREADS, 4)
void dcm2kp_kernel(const float* __restrict__ Rk,
                   const float* __restrict__ tfRk,
                   float* __restrict__ out)
{
    const int bid = blockIdx.x;          // [0, 2048)
    const int s   = bid >> 10;           // stack: 0 = Rk, 1 = tf_Rk
    const int bk  = bid & 1023;          // map index within stack

    const float* __restrict__ in = (s ? tfRk : Rk) + (size_t)bk * HW;
    float* __restrict__ dkout = out + (size_t)s * DK_ELEMS + (size_t)bk * HW;

    const int t = threadIdx.x;

    const float4* __restrict__ in4 = reinterpret_cast<const float4*>(in);
    float4* __restrict__ out4 = reinterpret_cast<float4*>(dkout);

    // ---- Phase 1: batch ALL loads up front (MLP = 6 per thread) ----
    float4 v[NIT];
    #pragma unroll
    for (int it = 0; it < NIT; ++it) {
        v[it] = __ldcs(&in4[t + it * NTHREADS]);   // streaming read: no reuse
    }

    // ---- Phase 2: sigmoid -> immediate store -> accumulate ----
    float zs = 0.0f, kxs = 0.0f, kys = 0.0f;

    #pragma unroll
    for (int it = 0; it < NIT; ++it) {
        const int j = t + it * NTHREADS;     // float4 index, [0, 2304)
        const int e = j << 2;                // element index, [0, 9216)

        // fast sigmoid (MUFU EX2 + RCP); rel err ~5e-7, fine for 1e-3 tol
        const float d0 = 1.0f / (1.0f + __expf(-v[it].x));
        const float d1 = 1.0f / (1.0f + __expf(-v[it].y));
        const float d2 = 1.0f / (1.0f + __expf(-v[it].z));
        const float d3 = 1.0f / (1.0f + __expf(-v[it].w));

        out4[j] = make_float4(d0, d1, d2, d3);   // default policy: L2-resident

        // 4 consecutive elements share the row (96 % 4 == 0, e % 4 == 0)
        const int h  = e / 96;
        const int w0 = e - h * 96;

        const float s4 = (d0 + d1) + (d2 + d3);
        zs  += s4;
        kxs += fmaf((float)w0, s4, d1 + 2.0f * d2 + 3.0f * d3);
        kys += fmaf((float)h, s4, 0.0f);
    }

    // ---- Phase 3: block reduction ----
    #pragma unroll
    for (int o = 16; o > 0; o >>= 1) {
        zs  += __shfl_down_sync(0xffffffffu, zs,  o);
        kxs += __shfl_down_sync(0xffffffffu, kxs, o);
        kys += __shfl_down_sync(0xffffffffu, kys, o);
    }

    __shared__ double sz[12], sx[12], sy[12];
    const int wid = t >> 5, lid = t & 31;
    if (lid == 0) { sz[wid] = (double)zs; sx[wid] = (double)kxs; sy[wid] = (double)kys; }
    __syncthreads();

    // ---- Phase 4: decode tail (thread 0) ----
    if (t == 0) {
        double z = 0.0, x = 0.0, y = 0.0;
        #pragma unroll
        for (int i = 0; i < 12; ++i) { z += sz[i]; x += sx[i]; y += sy[i]; }

        // jnp.round == round-half-to-even == rintf (default rounding mode)
        const float xr = rintf((float)(x / z));
        const float yr = rintf((float)(y / z));

        int wi = (int)xr; wi = wi < 0 ? 0 : (wi > 95 ? 95 : wi);
        int hi = (int)yr; hi = hi < 0 ? 0 : (hi > 95 ? 95 : hi);

        // gathered d: precise sigmoid (trunc boundaries are sensitive)
        const float dg = 1.0f / (1.0f + expf(-in[hi * 96 + wi]));

        const int b = bk >> 6;   // bk / 64
        const int k = bk & 63;   // bk % 64

        float* __restrict__ kpbase = out + 2 * DK_ELEMS + (size_t)s * KP_ELEMS
                                   + (size_t)b * (3 * K_DIM * 2);
        float* __restrict__ zbase  = out + 2 * DK_ELEMS + 2 * KP_ELEMS
                                   + (size_t)s * Z_ELEMS;

        // kp
        kpbase[k * 2 + 0] = xr;
        kpbase[k * 2 + 1] = yr;
        // kp1 = trunc(kp + kp*d)
        kpbase[(K_DIM + k) * 2 + 0] = truncf(xr + xr * dg);
        kpbase[(K_DIM + k) * 2 + 1] = truncf(yr + yr * dg);
        // kp2 = trunc(kp - kp*d)
        kpbase[(2 * K_DIM + k) * 2 + 0] = truncf(xr - xr * dg);
        kpbase[(2 * K_DIM + k) * 2 + 1] = truncf(yr - yr * dg);

        zbase[b * K_DIM + k] = (float)z;
    }
}

extern "C" void kernel_launch(void* const* d_in, const int* in_sizes, int n_in,
                              void* d_out, int out_size)
{
    (void)in_sizes; (void)n_in; (void)out_size;
    const float* Rk   = (const float*)d_in[0];
    const float* tfRk = (const float*)d_in[1];
    float* out = (float*)d_out;

    dcm2kp_kernel<<<2 * MAPS, NTHREADS>>>(Rk, tfRk, out);
}